// round 17
// baseline (speedup 1.0000x reference)
#include <cuda_runtime.h>
#include <cuda_fp16.h>
#include <cstdint>

#define EMBED   2048
#define NHEAD   32
#define HD      64
#define BATCH   2
#define SEQ     2048
#define MROWS   (BATCH*SEQ)      // 4096
#define QSCALE  (1.44269504088896f / 128.0f)   // log2(e)/sqrt(64)/16

// --- GEMM tiling: CTA 128x128, 8 warps (2x4), warp tile 64x32, 2 CTAs/SM ---
#define TM      128
#define TN      128
#define KC      64
#define ROWB    144
#define A_BYTES (TM*ROWB)        // 18432
#define B_BYTES (TN*ROWB)        // 18432
#define STAGE_BYTES (A_BYTES + B_BYTES)   // 36864
#define GSMEM   (3*STAGE_BYTES)           // 110592

// --- attention smem: 144B rows, Q[128] + 2 stages of (K[64]+V[64]) ---
#define AQ144     (128*144)               // 18432
#define ASTG      (128*144)               // 18432 (K 9216 + V 9216)
#define ATTN_SMEM (AQ144 + 2*ASTG)        // 55296

// Scratch (device globals: no runtime allocation allowed)
__device__ __align__(16) __half g_xh[(size_t)MROWS*EMBED];
__device__ __align__(16) __half g_qb[(size_t)MROWS*EMBED];
__device__ __align__(16) __half g_kb[(size_t)MROWS*EMBED];
__device__ __align__(16) __half g_vb[(size_t)MROWS*EMBED];
__device__ __align__(16) __half g_ctx[(size_t)MROWS*EMBED];
__device__ __align__(16) __half g_wq[(size_t)EMBED*EMBED];
__device__ __align__(16) __half g_wk[(size_t)EMBED*EMBED];
__device__ __align__(16) __half g_wv[(size_t)EMBED*EMBED];
__device__ __align__(16) __half g_wo[(size_t)EMBED*EMBED];

// ---------------------------------------------------------------------------
__device__ __forceinline__ uint32_t smem_u32(const void* p) {
    uint32_t a;
    asm("{ .reg .u64 t; cvta.to.shared.u64 t, %1; cvt.u32.u64 %0, t; }"
        : "=r"(a) : "l"(p));
    return a;
}

#define LDSM_X4(r, addr) \
    asm volatile("ldmatrix.sync.aligned.m8n8.x4.shared.b16 {%0,%1,%2,%3}, [%4];" \
        : "=r"((r)[0]), "=r"((r)[1]), "=r"((r)[2]), "=r"((r)[3]) : "r"(addr))
#define LDSM_X4T(r, addr) \
    asm volatile("ldmatrix.sync.aligned.m8n8.x4.trans.shared.b16 {%0,%1,%2,%3}, [%4];" \
        : "=r"((r)[0]), "=r"((r)[1]), "=r"((r)[2]), "=r"((r)[3]) : "r"(addr))

#define MMA16816(d, a, b0, b1) \
    asm volatile("mma.sync.aligned.m16n8k16.row.col.f32.f16.f16.f32 " \
        "{%0,%1,%2,%3}, {%4,%5,%6,%7}, {%8,%9}, {%0,%1,%2,%3};" \
        : "+f"((d)[0]), "+f"((d)[1]), "+f"((d)[2]), "+f"((d)[3]) \
        : "r"((a)[0]), "r"((a)[1]), "r"((a)[2]), "r"((a)[3]), "r"(b0), "r"(b1))

__device__ __forceinline__ uint32_t packh(float x, float y) {
    __half2 t = __floats2half2_rn(x, y);
    return *reinterpret_cast<uint32_t*>(&t);
}
__device__ __forceinline__ uint32_t ex2h2(uint32_t v) {
    uint32_t o;
    asm("ex2.approx.f16x2 %0, %1;" : "=r"(o) : "r"(v));
    return o;
}

// ---- TMA bulk + mbarrier (base sm_90 PTX) ----
#define BULKCP(d, s, mb) \
    asm volatile("cp.async.bulk.shared::cluster.global.mbarrier::complete_tx::bytes " \
        "[%0], [%1], 128, [%2];" :: "r"(d), "l"(s), "r"(mb) : "memory")
#define MB_INIT(a, c) \
    asm volatile("mbarrier.init.shared.b64 [%0], %1;" :: "r"(a), "r"(c) : "memory")
#define MB_EXPECT(a, b) \
    asm volatile("mbarrier.arrive.expect_tx.shared.b64 _, [%0], %1;" \
        :: "r"(a), "r"(b) : "memory")
#define MB_WAIT(a, p) \
    asm volatile("{\n\t.reg .pred P;\n\tWL_%=:\n\t" \
        "mbarrier.try_wait.parity.acquire.cta.shared::cta.b64 P, [%0], %1;\n\t" \
        "@!P bra WL_%=;\n\t}" :: "r"(a), "r"((unsigned)(p)) : "memory")

// ---------------------------------------------------------------------------
// Fused fp32 -> fp16 conversion of x + 4 weights (float4 granularity).
// ---------------------------------------------------------------------------
#define XT4 ((MROWS*EMBED)/4)
#define WT4 ((EMBED*EMBED)/4)
#define CONV_TASKS (XT4 + 4*WT4)

__global__ void conv_all(const float* __restrict__ x,
                         const float* __restrict__ wq, const float* __restrict__ wk,
                         const float* __restrict__ wv, const float* __restrict__ wo,
                         __half* __restrict__ xh,
                         __half* __restrict__ oq, __half* __restrict__ ok,
                         __half* __restrict__ ov, __half* __restrict__ oo)
{
    int idx = blockIdx.x * 256 + threadIdx.x;
    if (idx >= CONV_TASKS) return;
    const float* src; __half* dst; size_t rel;
    if (idx < XT4) {
        src = x; dst = xh; rel = (size_t)idx;
    } else {
        int j = idx - XT4;
        int seg = j >> 20;
        rel = (size_t)(j & (WT4 - 1));
        src = (seg == 0) ? wq : (seg == 1) ? wk : (seg == 2) ? wv : wo;
        dst = (seg == 0) ? oq : (seg == 1) ? ok : (seg == 2) ? ov : oo;
    }
    float4 v = *(const float4*)(src + rel * 4);
    uint2 o;
    o.x = packh(v.x, v.y);
    o.y = packh(v.z, v.w);
    *(uint2*)(dst + rel * 4) = o;
}

// ---------------------------------------------------------------------------
// HMMA fp16 GEMM, TMA-bulk-fed. MODE 0: QKV (fp16 out); MODE 1: out (fp32).
// ---------------------------------------------------------------------------
template<int MODE>
__global__ __launch_bounds__(256, 2)
void gemm_tpl(const __half* __restrict__ A,
              const __half* __restrict__ B0, const __half* __restrict__ B1,
              const __half* __restrict__ B2,
              const float* __restrict__ bi0, const float* __restrict__ bi1,
              const float* __restrict__ bi2,
              __half* __restrict__ C0, __half* __restrict__ C1,
              __half* __restrict__ C2, float* __restrict__ Cf)
{
    const int z = (MODE == 0) ? blockIdx.z : 0;
    const __half* B   = (z == 0) ? B0 : (z == 1) ? B1 : B2;
    const float* bias = (z == 0) ? bi0 : (z == 1) ? bi1 : bi2;
    __half* C         = (z == 0) ? C0 : (z == 1) ? C1 : C2;
    const float scale = (MODE == 0 && z == 0) ? QSCALE : 1.0f;

    extern __shared__ char dsm[];
    __shared__ __align__(8) uint64_t s_mb[3];
    const uint32_t sbase0 = smem_u32(dsm);
    const uint32_t mbb    = smem_u32(s_mb);
    const int tid    = threadIdx.x;
    const int warp   = tid >> 5;
    const int lane   = tid & 31;
    const int warp_m = warp >> 2;
    const int warp_n = warp & 3;
    const int tm0    = blockIdx.y * TM;
    const int tn0    = blockIdx.x * TN;
    const int nchunk = EMBED / KC;       // 32

    // per-thread bulk row (1 of 256 rows per chunk)
    const __half* rowsrc = (tid < 128)
        ? (A + (size_t)(tm0 + tid) * EMBED)
        : (B + (size_t)(tn0 + (tid & 127)) * EMBED);
    const uint32_t rowdst = ((tid < 128) ? 0u : (uint32_t)A_BYTES)
                            + (uint32_t)(tid & 127) * ROWB;

#define LOAD_CHUNK(ci) \
    BULKCP(sbase0 + ((ci) % 3) * STAGE_BYTES + rowdst, \
           rowsrc + (ci) * KC, mbb + ((ci) % 3) * 8)

    const int g  = lane >> 3;
    const int lr = lane & 7;
    uint32_t aoff[4], boff[2];
#pragma unroll
    for (int mi = 0; mi < 4; mi++)
        aoff[mi] = (uint32_t)((warp_m * 64 + mi * 16 + (g & 1) * 8 + lr) * ROWB
                              + (g >> 1) * 16);
#pragma unroll
    for (int nj = 0; nj < 2; nj++)
        boff[nj] = (uint32_t)(A_BYTES
                              + (warp_n * 32 + nj * 16 + (g & 1) * 8 + lr) * ROWB
                              + (g >> 1) * 16);

    float acc[4][4][4];
#pragma unroll
    for (int mi = 0; mi < 4; mi++)
#pragma unroll
        for (int n8 = 0; n8 < 4; n8++)
#pragma unroll
            for (int e = 0; e < 4; e++) acc[mi][n8][e] = 0.0f;

#define LOAD_FRAGS(buf, sb, ks) do {                                             \
    _Pragma("unroll")                                                            \
    for (int mi_ = 0; mi_ < 4; mi_++)                                            \
        LDSM_X4(aF[buf][mi_], (sb) + aoff[mi_] + (ks) * 32);                     \
    _Pragma("unroll")                                                            \
    for (int nj_ = 0; nj_ < 2; nj_++)                                            \
        LDSM_X4(bF[buf][nj_], (sb) + boff[nj_] + (ks) * 32);                     \
} while (0)

#define MMA_BLOCK(buf) do {                                                      \
    _Pragma("unroll")                                                            \
    for (int mi_ = 0; mi_ < 4; mi_++)                                            \
        _Pragma("unroll")                                                        \
        for (int n8_ = 0; n8_ < 4; n8_++)                                        \
            MMA16816(acc[mi_][n8_], aF[buf][mi_],                                \
                     bF[buf][n8_ >> 1][n8_ & 1],                                 \
                     bF[buf][n8_ >> 1][2 + (n8_ & 1)]);                          \
} while (0)

    uint32_t aF[2][4][4], bF[2][2][4];
    unsigned par3 = 0;

    // prologue: init + expect chunks 0,1,2 (single thread, pre-barrier: race-free)
    if (tid == 0) {
        MB_INIT(mbb + 0, 1);  MB_INIT(mbb + 8, 1);  MB_INIT(mbb + 16, 1);
        MB_EXPECT(mbb + 0, 32768);
        MB_EXPECT(mbb + 8, 32768);
        MB_EXPECT(mbb + 16, 32768);
    }
    __syncthreads();
    LOAD_CHUNK(0); LOAD_CHUNK(1); LOAD_CHUNK(2);
    MB_WAIT(mbb + 0, 0); par3 ^= 1u;
    if (tid == 0) MB_EXPECT(mbb + 0, 32768);       // chunk 3 (bulks after B_0)
    LOAD_FRAGS(0, sbase0, 0);

    for (int i = 0; i < nchunk; i++) {
        const uint32_t sb = sbase0 + (i % 3) * STAGE_BYTES;

        LOAD_FRAGS(1, sb, 1);  MMA_BLOCK(0);
        LOAD_FRAGS(0, sb, 2);  MMA_BLOCK(1);
        LOAD_FRAGS(1, sb, 3);  MMA_BLOCK(0);

        if (i + 1 < nchunk) {
            const int s1 = (i + 1) % 3;
            MB_WAIT(mbb + 8 * s1, (par3 >> s1) & 1); par3 ^= 1u << s1;
            __syncthreads();
            if (i + 3 < nchunk) LOAD_CHUNK(i + 3);
            if (tid == 0 && i + 4 < nchunk)
                MB_EXPECT(mbb + 8 * ((i + 4) % 3), 32768);
            LOAD_FRAGS(0, sbase0 + s1 * STAGE_BYTES, 0);
        }
        MMA_BLOCK(1);   // ks3
    }
#undef LOAD_CHUNK
#undef LOAD_FRAGS
#undef MMA_BLOCK

    const int qr = lane >> 2;
    const int qc = (lane & 3) * 2;
#pragma unroll
    for (int mi = 0; mi < 4; mi++) {
        int row = tm0 + warp_m * 64 + mi * 16 + qr;
#pragma unroll
        for (int n8 = 0; n8 < 4; n8++) {
            int col = tn0 + warp_n * 32 + n8 * 8 + qc;
            float b0 = __ldg(bias + col);
            float b1 = __ldg(bias + col + 1);
            if (MODE == 0) {
                *(uint32_t*)(C + (size_t)row * EMBED + col) =
                    packh((acc[mi][n8][0] + b0) * scale,
                          (acc[mi][n8][1] + b1) * scale);
                *(uint32_t*)(C + (size_t)(row + 8) * EMBED + col) =
                    packh((acc[mi][n8][2] + b0) * scale,
                          (acc[mi][n8][3] + b1) * scale);
            } else {
                float2 o0 = { acc[mi][n8][0] + b0, acc[mi][n8][1] + b1 };
                float2 o1 = { acc[mi][n8][2] + b0, acc[mi][n8][3] + b1 };
                *(float2*)(Cf + (size_t)row * EMBED + col) = o0;
                *(float2*)(Cf + (size_t)(row + 8) * EMBED + col) = o1;
            }
        }
    }
}

// ---------------------------------------------------------------------------
// Tensor-core causal flash attention (fp16), TMA-bulk-fed, base-2 softmax.
// 144B-padded rows (no swizzle). Row sums via ones-column MMA.
// ---------------------------------------------------------------------------
__global__ __launch_bounds__(256, 2)
void attn_tc(const __half* __restrict__ Qg, const __half* __restrict__ Kg,
             const __half* __restrict__ Vg, __half* __restrict__ Ctx)
{
    extern __shared__ char smbuf[];
    __shared__ __align__(8) uint64_t s_amb[2];
    const uint32_t sbase = smem_u32(smbuf);
    const uint32_t ambb  = smem_u32(s_amb);
    const uint32_t kvb   = sbase + AQ144;
    const int tid  = threadIdx.x;
    const int lane = tid & 31;
    const int w    = tid >> 5;
    const int qt   = gridDim.x - 1 - blockIdx.x;   // heavy tiles first
    const int bh   = blockIdx.y;
    const int b    = bh >> 5;
    const int h    = bh & 31;
    const int q0   = qt * 128;

    const size_t rowbase = (size_t)(b * SEQ);
    const __half* Qb = Qg + (rowbase + q0) * EMBED + h * HD;
    const __half* Kb = Kg + rowbase * EMBED + h * HD;
    const __half* Vb = Vg + rowbase * EMBED + h * HD;

    const int ntiles = 2 * qt + 2;

    // prologue: init + expects (tile0 shares mb0 with Q)
    if (tid == 0) {
        MB_INIT(ambb, 1);  MB_INIT(ambb + 8, 1);
        MB_EXPECT(ambb, 32768);        // Q (16K) + tile0 (16K)
        MB_EXPECT(ambb + 8, 16384);    // tile1
    }
    __syncthreads();
    // Q rows via threads 0-127, tile0 K/V rows via threads 128-255
    if (tid < 128) {
        BULKCP(sbase + (uint32_t)tid * 144, Qb + (size_t)tid * EMBED, ambb);
    } else {
        int t = tid - 128;
        const __half* s = (t < 64) ? (Kb + (size_t)t * EMBED)
                                   : (Vb + (size_t)(t - 64) * EMBED);
        uint32_t d = kvb + ((t < 64) ? 0u : 9216u) + (uint32_t)(t & 63) * 144;
        BULKCP(d, s, ambb);
    }

    float oacc[8][4];
#pragma unroll
    for (int j = 0; j < 8; j++)
#pragma unroll
        for (int e = 0; e < 4; e++) oacc[j][e] = 0.0f;
    float lacc[4] = {0.0f, 0.0f, 0.0f, 0.0f};
    uint32_t aq[4][4];
    const uint32_t one2 = packh(1.0f, 1.0f);
    unsigned par2 = 0;

    const int la7 = lane & 7, lb3 = (lane >> 3) & 1, lb4 = (lane >> 4) & 1;
    const int qrow = w * 16 + la7 + lb3 * 8, qcolb = lb4 * 16;
    const int krow = la7 + lb4 * 8,          kcolb = lb3 * 16;
    const int vrow = la7 + lb3 * 8,          vcolb = lb4 * 16;
    const int wrow_min = q0 + w * 16;
    const int wrow_max = wrow_min + 15;

#define KADDR(it) (kst + (((it) & 3) * 16 + krow) * 144 + ((it) >> 2) * 32 + kcolb)
#define VADDR(it) (kst + 9216 + (((it) >> 2) * 16 + vrow) * 144 + ((it) & 3) * 32 + vcolb)

    for (int jt = 0; jt < ntiles; jt++) {
        // issue next tile's bulks (expect posted >=1 barrier earlier)
        if (jt + 1 < ntiles && tid < 128) {
            int t = tid;
            const __half* s = (t < 64)
                ? (Kb + (size_t)((jt + 1) * 64 + t) * EMBED)
                : (Vb + (size_t)((jt + 1) * 64 + (t - 64)) * EMBED);
            uint32_t d = kvb + (uint32_t)((jt + 1) & 1) * ASTG
                         + ((t < 64) ? 0u : 9216u) + (uint32_t)(t & 63) * 144;
            BULKCP(d, s, ambb + 8 * ((jt + 1) & 1));
        }
        const int s0 = jt & 1;
        MB_WAIT(ambb + 8 * s0, (par2 >> s0) & 1); par2 ^= 1u << s0;
        if (tid == 0 && jt + 2 < ntiles) MB_EXPECT(ambb + 8 * s0, 16384);

        if (jt == 0) {
#pragma unroll
            for (int ks = 0; ks < 4; ks++)
                LDSM_X4(aq[ks], sbase + qrow * 144 + ks * 32 + qcolb);
        }

        const uint32_t kst = kvb + (uint32_t)s0 * ASTG;
        if (jt * 64 <= wrow_max) {
            // ---- S = Q K^T (log2-scaled) ----
            float sa[8][4];
#pragma unroll
            for (int j = 0; j < 8; j++)
#pragma unroll
                for (int e = 0; e < 4; e++) sa[j][e] = 0.0f;
            {
                uint32_t kf[2][4];
                LDSM_X4(kf[0], KADDR(0));
#pragma unroll
                for (int it = 0; it < 16; it++) {
                    if (it < 15) LDSM_X4(kf[(it + 1) & 1], KADDR(it + 1));
                    const int ks = it >> 2, jp = it & 3;
                    MMA16816(sa[2 * jp],     aq[ks], kf[it & 1][0], kf[it & 1][1]);
                    MMA16816(sa[2 * jp + 1], aq[ks], kf[it & 1][2], kf[it & 1][3]);
                }
            }

            // causal mask (2^-30000 -> 0 in fp16)
            if (jt * 64 + 63 > wrow_min) {
#pragma unroll
                for (int j = 0; j < 8; j++) {
                    int colb = jt * 64 + j * 8 + 2 * (lane & 3);
                    int r0g  = wrow_min + (lane >> 2);
#pragma unroll
                    for (int e = 0; e < 4; e++) {
                        int col = colb + (e & 1);
                        int row = r0g + (e >> 1) * 8;
                        if (col > row) sa[j][e] = -30000.0f;
                    }
                }
            }

            // ---- P = 2^S fp16x2 (= MMA A-fragments) ----
            uint32_t pa[4][4];
#pragma unroll
            for (int j = 0; j < 8; j++) {
                uint32_t e01 = ex2h2(packh(sa[j][0], sa[j][1]));
                uint32_t e23 = ex2h2(packh(sa[j][2], sa[j][3]));
                pa[j >> 1][(j & 1) * 2 + 0] = e01;
                pa[j >> 1][(j & 1) * 2 + 1] = e23;
            }

            // ---- PV + ones-column row-sum MMA ----
            {
                uint32_t vF[2][4];
                LDSM_X4T(vF[0], VADDR(0));
#pragma unroll
                for (int it = 0; it < 16; it++) {
                    if (it < 15) LDSM_X4T(vF[(it + 1) & 1], VADDR(it + 1));
                    const int t = it >> 2, gg = it & 3;
                    if (gg == 0) MMA16816(lacc, pa[t], one2, one2);
                    MMA16816(oacc[2*gg],   pa[t], vF[it & 1][0], vF[it & 1][1]);
                    MMA16816(oacc[2*gg+1], pa[t], vF[it & 1][2], vF[it & 1][3]);
                }
            }
        }
        __syncthreads();
    }
#undef KADDR
#undef VADDR

    float inv0 = 1.0f / lacc[0], inv1 = 1.0f / lacc[2];
    size_t grow0 = rowbase + q0 + w * 16 + (lane >> 2);
    __half* base0 = Ctx + grow0 * EMBED + h * HD + 2 * (lane & 3);
    __half* base1 = base0 + (size_t)8 * EMBED;
#pragma unroll
    for (int j = 0; j < 8; j++) {
        *(uint32_t*)(base0 + j * 8) = packh(oacc[j][0] * inv0, oacc[j][1] * inv0);
        *(uint32_t*)(base1 + j * 8) = packh(oacc[j][2] * inv1, oacc[j][3] * inv1);
    }
}

// ---------------------------------------------------------------------------
extern "C" void kernel_launch(void* const* d_in, const int* in_sizes, int n_in,
                              void* d_out, int out_size)
{
    const float* x  = (const float*)d_in[0];
    const float* Wq = (const float*)d_in[1];
    const float* bq = (const float*)d_in[2];
    const float* Wk = (const float*)d_in[3];
    const float* bk = (const float*)d_in[4];
    const float* Wv = (const float*)d_in[5];
    const float* bv = (const float*)d_in[6];
    const float* Wo = (const float*)d_in[7];
    const float* bo = (const float*)d_in[8];
    float* out = (float*)d_out;

    __half *xh, *qb, *kb, *vb, *ctx, *wq, *wk, *wv, *wo;
    cudaGetSymbolAddress((void**)&xh,  g_xh);
    cudaGetSymbolAddress((void**)&qb,  g_qb);
    cudaGetSymbolAddress((void**)&kb,  g_kb);
    cudaGetSymbolAddress((void**)&vb,  g_vb);
    cudaGetSymbolAddress((void**)&ctx, g_ctx);
    cudaGetSymbolAddress((void**)&wq,  g_wq);
    cudaGetSymbolAddress((void**)&wk,  g_wk);
    cudaGetSymbolAddress((void**)&wv,  g_wv);
    cudaGetSymbolAddress((void**)&wo,  g_wo);

    cudaFuncSetAttribute(attn_tc, cudaFuncAttributeMaxDynamicSharedMemorySize,
                         ATTN_SMEM);
    cudaFuncSetAttribute(gemm_tpl<0>, cudaFuncAttributeMaxDynamicSharedMemorySize,
                         GSMEM);
    cudaFuncSetAttribute(gemm_tpl<1>, cudaFuncAttributeMaxDynamicSharedMemorySize,
                         GSMEM);

    conv_all<<<(CONV_TASKS + 255) / 256, 256>>>(x, Wq, Wk, Wv, Wo,
                                                xh, wq, wk, wv, wo);

    dim3 qkvgrid(EMBED / TN, MROWS / TM, 3);     // (16, 32, 3)
    gemm_tpl<0><<<qkvgrid, 256, GSMEM>>>(xh, wq, wk, wv, bq, bk, bv,
                                         qb, kb, vb, nullptr);

    dim3 agrid(SEQ / 128, BATCH * NHEAD);        // (16, 64)
    attn_tc<<<agrid, 256, ATTN_SMEM>>>(qb, kb, vb, ctx);

    dim3 ogrid(EMBED / TN, MROWS / TM);          // (16, 32)
    gemm_tpl<1><<<ogrid, 256, GSMEM>>>(ctx, wo, nullptr, nullptr, bo, nullptr,
                                       nullptr, nullptr, nullptr, nullptr, out);
}